// round 16
// baseline (speedup 1.0000x reference)
#include <cuda_runtime.h>
#include <cuda_fp16.h>
#include <cstdint>

#define N_PTS 8192
#define DIMK  512
#define KNN   10
#define NSEL  16                 // refined candidate count per row
#define SELK  6                  // coarse candidates kept per (row, half, tile)
#define NTILE (N_PTS / 128)      // 64 column tiles per row
#define CPT   (2 * SELK)         // candidates per (row, tile) = 12
#define QSCALE 20.0f
#define INVS2  (1.0f / (QSCALE * QSCALE))

// Static device scratch (no runtime allocation allowed)
__device__ float    g_sq[N_PTS];
__device__ int8_t   g_xq[(size_t)N_PTS * DIMK];    // 4 MB int8 quantized x
// 32-bit coarse keys: (d2_bits & ~0x7F) | local_col(7b) : 25 MB
__device__ uint32_t g_cand[(size_t)N_PTS * NTILE * CPT];

// ---------------------------------------------------------------------------
// Kernel 1: prep — int8 quantization (scale 20, clamp +-127) + fp64 norms.
// Coarse d2 noise sigma ~0.65 vs ~8-unit rank-10..16 gap: 8.6-sigma margin,
// and the exact fp32 refine re-decides everything inside coarse-top-16.
// ---------------------------------------------------------------------------
__global__ void __launch_bounds__(256) prep_kernel(const float* __restrict__ x) {
    int row  = blockIdx.x * 8 + (threadIdx.x >> 5);
    int lane = threadIdx.x & 31;
    const float4* xr = (const float4*)(x + (size_t)row * DIMK);
    double s0 = 0.0, s1 = 0.0, s2 = 0.0, s3 = 0.0;
#pragma unroll
    for (int t = 0; t < 4; t++) {
        int e = lane + t * 32;
        float4 v = xr[e];
        int q0 = max(-127, min(127, __float2int_rn(v.x * QSCALE)));
        int q1 = max(-127, min(127, __float2int_rn(v.y * QSCALE)));
        int q2 = max(-127, min(127, __float2int_rn(v.z * QSCALE)));
        int q3 = max(-127, min(127, __float2int_rn(v.w * QSCALE)));
        uint32_t packed = (uint32_t)(q0 & 0xFF) | ((uint32_t)(q1 & 0xFF) << 8)
                        | ((uint32_t)(q2 & 0xFF) << 16) | ((uint32_t)(q3 & 0xFF) << 24);
        *(uint32_t*)&g_xq[(size_t)row * DIMK + e * 4] = packed;
        s0 += (double)v.x * v.x;
        s1 += (double)v.y * v.y;
        s2 += (double)v.z * v.z;
        s3 += (double)v.w * v.w;
    }
    double s = (s0 + s1) + (s2 + s3);
#pragma unroll
    for (int o = 16; o; o >>= 1)
        s += __shfl_xor_sync(0xFFFFFFFFu, s, o);
    if (lane == 0) g_sq[row] = (float)s;
}

// ---------------------------------------------------------------------------
// IMMA helpers. s8 k32 fragments are byte-identical to fp16 k16 fragments,
// so ldmatrix addressing / swizzle carry over unchanged.
// ---------------------------------------------------------------------------
__device__ __forceinline__ void ldsm4_addr(uint32_t& r0, uint32_t& r1,
                                           uint32_t& r2, uint32_t& r3, uint32_t a) {
    asm volatile("ldmatrix.sync.aligned.m8n8.x4.shared.b16 {%0,%1,%2,%3}, [%4];"
                 : "=r"(r0), "=r"(r1), "=r"(r2), "=r"(r3) : "r"(a));
}
__device__ __forceinline__ void ldsm2_addr(uint32_t& r0, uint32_t& r1, uint32_t a) {
    asm volatile("ldmatrix.sync.aligned.m8n8.x2.shared.b16 {%0,%1}, [%2];"
                 : "=r"(r0), "=r"(r1) : "r"(a));
}
__device__ __forceinline__ void mma16832s8(int c[4], const uint32_t a[4],
                                           const uint32_t b[2]) {
    asm volatile(
        "mma.sync.aligned.m16n8k32.row.col.s32.s8.s8.s32 "
        "{%0,%1,%2,%3}, {%4,%5,%6,%7}, {%8,%9}, {%0,%1,%2,%3};"
        : "+r"(c[0]), "+r"(c[1]), "+r"(c[2]), "+r"(c[3])
        : "r"(a[0]), "r"(a[1]), "r"(a[2]), "r"(a[3]), "r"(b[0]), "r"(b[1]));
}

// ---------------------------------------------------------------------------
// Kernel 2: COARSE int8 distance GEMM + fused per-tile candidate selection.
// KCHUNK = 128 int8 = 128 B rows (SW128-native), NCHUNK = 4, stages 3x32 KB,
// one sync per chunk, occ 2. Keys: (d2_bits & ~0x7F) | local_col.
// ---------------------------------------------------------------------------
#define KCHUNK      128
#define NCHUNK      (DIMK / KCHUNK)         // 4
#define MATB        16384                   // 128 rows x 128 B
#define STAGEB      (2 * MATB)              // Aq + Bq = 32 KB
#define NSTAGE      3
#define SPITCH      132                     // stage pitch (floats, 16B-aligned)
#define DSMEM_BYTES (NSTAGE * STAGEB)       // 96 KB

__device__ __forceinline__ uint32_t sw128(uint32_t row, uint32_t cb) {
    return row * 128u + (cb ^ ((row & 7u) << 4));
}

__device__ __forceinline__ void issue_chunk(const char* xbase,
                                            const uint32_t srcoff[8],
                                            const uint32_t dstoff[8],
                                            uint32_t bufbase, uint32_t kbyte) {
#pragma unroll
    for (int i = 0; i < 8; i++) {
        asm volatile("cp.async.cg.shared.global [%0], [%1], 16;"
                     :: "r"(bufbase + dstoff[i]),
                        "l"(xbase + srcoff[i] + kbyte));
    }
    asm volatile("cp.async.commit_group;" ::: "memory");
}

// Branch-gated min/max cascade insert into ascending keys[SELK] (32-bit)
__device__ __forceinline__ void ins6u(uint32_t keys[SELK], uint32_t k) {
    if (k < keys[SELK - 1]) {
        uint32_t c = k;
#pragma unroll
        for (int p = 0; p < SELK; p++) {
            uint32_t lo = min(keys[p], c);
            c = max(keys[p], c);
            keys[p] = lo;
        }
    }
}

__global__ void __launch_bounds__(256, 2) dist_mma_kernel() {
    int bid = blockIdx.x;
    int ib = 0, base = 0;
    while (base + (NTILE - ib) <= bid) { base += NTILE - ib; ++ib; }
    int jb = ib + (bid - base);

    extern __shared__ __align__(1024) unsigned char dsm[];
    __shared__ __align__(16) float s_sqi[128];
    __shared__ __align__(16) float s_sqj[128];

    const int i0 = ib * 128;
    const int j0 = jb * 128;
    const int tid  = threadIdx.x;
    const int lane = tid & 31;
    const int warp = tid >> 5;
    const int wm = warp >> 2;
    const int wn = warp & 3;

    const uint32_t dsm_base = (uint32_t)__cvta_generic_to_shared(dsm);

    if (tid < 128) {
        s_sqi[tid] = g_sq[i0 + tid];
        s_sqj[tid] = g_sq[j0 + tid];
    }

    // Hoisted cp.async addressing: per chunk per matrix 128 rows x 8 16B segs
    uint32_t srcoff[8], dstoff[8];
#pragma unroll
    for (int i = 0; i < 8; i++) {
        int o   = tid + i * 256;        // 0..2047
        int mat = o >> 10;              // 0:Aq 1:Bq
        int r   = (o >> 3) & 127;
        int seg = o & 7;
        int rowbase = mat ? j0 : i0;
        srcoff[i] = (uint32_t)((rowbase + r) * DIMK + seg * 16);
        dstoff[i] = (uint32_t)(mat * MATB + sw128((uint32_t)r, (uint32_t)(seg * 16)));
    }
    const char* xbase = (const char*)g_xq;

    int acc[4][4][4];
#pragma unroll
    for (int a = 0; a < 4; a++)
#pragma unroll
        for (int b = 0; b < 4; b++)
#pragma unroll
            for (int c = 0; c < 4; c++) acc[a][b][c] = 0;

    issue_chunk(xbase, srcoff, dstoff, dsm_base, 0);
    issue_chunk(xbase, srcoff, dstoff, dsm_base + STAGEB, KCHUNK);

    const uint32_t Arow = (uint32_t)(wm * 64 + (lane & 15));
    const uint32_t Acb  = (uint32_t)((lane >> 4) * 16);
    const uint32_t Brow = (uint32_t)(wn * 32 + (lane & 7));
    const uint32_t Bcb  = (uint32_t)(((lane >> 3) & 1) * 16);

#pragma unroll
    for (int c = 0; c < NCHUNK; c++) {
        if (c < NCHUNK - 1) asm volatile("cp.async.wait_group 1;" ::: "memory");
        else                asm volatile("cp.async.wait_group 0;" ::: "memory");
        __syncthreads();   // stage c ready; also frees buffer (c-1)%3

        uint32_t stA = dsm_base + (c % NSTAGE) * STAGEB;
        uint32_t stB = stA + MATB;

#pragma unroll
        for (int ks = 0; ks < 4; ks++) {          // 4 x K=32 over 128B chunk
            uint32_t Aq[4][4], Bq[4][2];
            const uint32_t acol = (uint32_t)(ks * 32) + Acb;
            const uint32_t bcol = (uint32_t)(ks * 32) + Bcb;
#pragma unroll
            for (int mt = 0; mt < 4; mt++)
                ldsm4_addr(Aq[mt][0], Aq[mt][1], Aq[mt][2], Aq[mt][3],
                           stA + sw128(Arow + mt * 16, acol));
#pragma unroll
            for (int nt = 0; nt < 4; nt++)
                ldsm2_addr(Bq[nt][0], Bq[nt][1], stB + sw128(Brow + nt * 8, bcol));
#pragma unroll
            for (int mt = 0; mt < 4; mt++)
#pragma unroll
                for (int nt = 0; nt < 4; nt++)
                    mma16832s8(acc[mt][nt], Aq[mt], Bq[nt]);

            if (ks == 0 && c + 2 < NCHUNK)
                issue_chunk(xbase, srcoff, dstoff,
                            dsm_base + ((c + 2) % NSTAGE) * STAGEB,
                            (uint32_t)((c + 2) * KCHUNK));
        }
    }
    __syncthreads();   // mainloop reads done before smem reuse as stage

    // Stage coarse dot values as floats (x invs2), float2-packed
    float (*stage)[SPITCH] = (float(*)[SPITCH])dsm;
    const int r_in = lane >> 2;
    const int c_in = (lane & 3) * 2;
#pragma unroll
    for (int mt = 0; mt < 4; mt++) {
#pragma unroll
        for (int nt = 0; nt < 4; nt++) {
            int r  = wm * 64 + mt * 16 + r_in;
            int cc = wn * 32 + nt * 8 + c_in;
            *(float2*)&stage[r    ][cc] =
                make_float2((float)acc[mt][nt][0] * INVS2,
                            (float)acc[mt][nt][1] * INVS2);
            *(float2*)&stage[r + 8][cc] =
                make_float2((float)acc[mt][nt][2] * INVS2,
                            (float)acc[mt][nt][3] * INVS2);
        }
    }
    __syncthreads();

    const int rl   = tid >> 1;        // 0..127 (row for pass1 / col for pass2)
    const int half = tid & 1;
    const int hb   = half * 64;

    // ---- Pass 1: rows i. d2 = (sq_i - 2*dot) + sq_j ----
    {
        uint32_t keys[SELK];
#pragma unroll
        for (int q = 0; q < SELK; q++) keys[q] = 0xFFFFFFFFu;
        const float sqi_r = s_sqi[rl];
        for (int v4 = 0; v4 < 16; v4++) {
            float4 sv = *(const float4*)&stage[rl][hb + v4 * 4];
            float4 qj = *(const float4*)&s_sqj[hb + v4 * 4];
#pragma unroll
            for (int e = 0; e < 4; e++) {
                float s  = (&sv.x)[e];
                float qq = (&qj.x)[e];
                float d = fmaxf((sqi_r - 2.0f * s) + qq, 0.0f);
                uint32_t k = (__float_as_uint(d) & 0xFFFFFF80u)
                           | (uint32_t)(hb + v4 * 4 + e);
                ins6u(keys, k);
            }
        }
        uint32_t* dst =
            &g_cand[((size_t)(i0 + rl) * NTILE + jb) * CPT + half * SELK];
#pragma unroll
        for (int q = 0; q < SELK; q++) dst[q] = keys[q];
    }

    // ---- Pass 2: rows j (off-diagonal CTAs). d2 = (sq_j - 2*dot) + sq_i ----
    if (ib != jb) {
        uint32_t keys[SELK];
#pragma unroll
        for (int q = 0; q < SELK; q++) keys[q] = 0xFFFFFFFFu;
        const float sqj_c = s_sqj[rl];
        for (int v = 0; v < 64; v++) {
            int il = hb + v;
            float d = fmaxf((sqj_c - 2.0f * stage[il][rl]) + s_sqi[il], 0.0f);
            uint32_t k = (__float_as_uint(d) & 0xFFFFFF80u) | (uint32_t)il;
            ins6u(keys, k);
        }
        uint32_t* dst =
            &g_cand[((size_t)(j0 + rl) * NTILE + ib) * CPT + half * SELK];
#pragma unroll
        for (int q = 0; q < SELK; q++) dst[q] = keys[q];
    }
}

// ---------------------------------------------------------------------------
// Kernel 3 (FUSED): merge 64x12 coarse candidates -> top-16, exact fp32
// refine streamed from L2, select top-10, smooth. One block (128 thr)/row.
// ---------------------------------------------------------------------------
__device__ __forceinline__ void ins6ull(unsigned long long keys[SELK],
                                        unsigned long long key) {
    if (key < keys[SELK - 1]) {
        keys[SELK - 1] = key;
#pragma unroll
        for (int p = SELK - 1; p > 0; p--) {
            if (keys[p] < keys[p - 1]) {
                unsigned long long t = keys[p];
                keys[p] = keys[p - 1];
                keys[p - 1] = t;
            }
        }
    }
}

__global__ void __launch_bounds__(128) merge_refine_smooth_kernel(
        const float* __restrict__ x, float* __restrict__ out) {
    const int row = blockIdx.x;
    const int tid = threadIdx.x;
    const uint32_t* crow = g_cand + (size_t)row * NTILE * CPT;

    __shared__ __align__(16) float s_xi[DIMK];
    __shared__ unsigned long long sdata[128];
    __shared__ int s_idx[NSEL];
    __shared__ unsigned long long s_keys[NSEL];
    __shared__ int s_sel10[KNN];

    ((float4*)s_xi)[tid] = ((const float4*)(x + (size_t)row * DIMK))[tid];

    // Per-thread merge of 6 coarse keys (768 total = 6 x 128)
    unsigned long long keys[SELK];
#pragma unroll
    for (int i = 0; i < SELK; i++) keys[i] = 0xFFFFFFFFFFFFFFFFull;
#pragma unroll
    for (int q = 0; q < SELK; q++) {
        int pos = tid + q * 128;                 // 0..767
        uint32_t k32 = crow[pos];
        int tile = pos / CPT;
        unsigned gcol = (unsigned)(tile * 128) + (k32 & 127u);
        unsigned long long ukey =
            ((unsigned long long)(k32 & 0xFFFFFF80u) << 32) | gcol;
        ins6ull(keys, ukey);
    }

    // 16 rounds of block arg-min -> s_idx[0..15]
    for (int r = 0; r < NSEL; r++) {
        sdata[tid] = keys[0];
        __syncthreads();
#pragma unroll
        for (int s = 64; s > 0; s >>= 1) {
            if (tid < s) {
                unsigned long long o = sdata[tid + s];
                if (o < sdata[tid]) sdata[tid] = o;
            }
            __syncthreads();
        }
        unsigned long long win = sdata[0];
        if (tid == 0) s_idx[r] = (int)(win & 0xFFFFFFFFull);
        if (keys[0] == win) {
#pragma unroll
            for (int p = 0; p < SELK - 1; p++) keys[p] = keys[p + 1];
            keys[SELK - 1] = 0xFFFFFFFFFFFFFFFFull;
        }
        __syncthreads();
    }

    // Exact fp32 refine: 8 threads/candidate, rows streamed from L2
    {
        const int c  = tid >> 3;     // candidate 0..15
        const int cs = tid & 7;
        const float4* cr = (const float4*)(x + (size_t)s_idx[c] * DIMK);
        float d0 = 0.0f, d1 = 0.0f, d2a = 0.0f, d3 = 0.0f;
#pragma unroll
        for (int k = 0; k < 16; k++) {
            int q = cs + 8 * k;
            float4 xa = ((const float4*)s_xi)[q];
            float4 xb = cr[q];
            d0  = fmaf(xa.x, xb.x, d0);
            d1  = fmaf(xa.y, xb.y, d1);
            d2a = fmaf(xa.z, xb.z, d2a);
            d3  = fmaf(xa.w, xb.w, d3);
        }
        float dot = (d0 + d1) + (d2a + d3);
#pragma unroll
        for (int off = 4; off; off >>= 1)
            dot += __shfl_down_sync(0xFFFFFFFFu, dot, off, 8);
        if (cs == 0) {
            float d2 = fmaxf((g_sq[row] - 2.0f * dot) + g_sq[s_idx[c]], 0.0f);
            s_keys[c] = ((unsigned long long)__float_as_uint(d2) << 32)
                      | (unsigned)s_idx[c];
        }
    }
    __syncthreads();

    // Thread 0: select 10 smallest exact keys
    if (tid == 0) {
        bool used[NSEL];
#pragma unroll
        for (int c = 0; c < NSEL; c++) used[c] = false;
        for (int r = 0; r < KNN; r++) {
            unsigned long long best = 0xFFFFFFFFFFFFFFFFull;
            int bslot = 0;
            for (int c = 0; c < NSEL; c++) {
                if (!used[c] && s_keys[c] < best) { best = s_keys[c]; bslot = c; }
            }
            used[bslot] = true;
            s_sel10[r] = s_idx[bslot];
        }
    }
    __syncthreads();

    // Smoothing: winners re-read from global (x is 16 MB -> L2 resident)
    float4 acc = make_float4(0.0f, 0.0f, 0.0f, 0.0f);
#pragma unroll
    for (int r = 0; r < KNN; r++) {
        float4 v = ((const float4*)(x + (size_t)s_sel10[r] * DIMK))[tid];
        acc.x += v.x; acc.y += v.y; acc.z += v.z; acc.w += v.w;
    }
    float4 xi = ((const float4*)s_xi)[tid];
    const float w = 0.5f / (float)KNN;
    float4 o;
    o.x = 0.5f * xi.x + w * acc.x;
    o.y = 0.5f * xi.y + w * acc.y;
    o.z = 0.5f * xi.z + w * acc.z;
    o.w = 0.5f * xi.w + w * acc.w;
    ((float4*)(out + (size_t)row * DIMK))[tid] = o;
}

// ---------------------------------------------------------------------------
extern "C" void kernel_launch(void* const* d_in, const int* in_sizes, int n_in,
                              void* d_out, int out_size) {
    const float* x = (const float*)d_in[0];
    float* out = (float*)d_out;

    cudaFuncSetAttribute(dist_mma_kernel,
                         cudaFuncAttributeMaxDynamicSharedMemorySize, DSMEM_BYTES);

    prep_kernel<<<N_PTS / 8, 256>>>(x);
    dist_mma_kernel<<<NTILE * (NTILE + 1) / 2, 256, DSMEM_BYTES>>>();
    merge_refine_smooth_kernel<<<N_PTS, 128>>>(x, out);
}

// round 17
// speedup vs baseline: 1.5743x; 1.5743x over previous
#include <cuda_runtime.h>
#include <cuda_fp16.h>
#include <cstdint>

#define N_PTS 8192
#define DIMK  512
#define KNN   10
#define NSEL  16                 // refined candidate count per row
#define SELK  6                  // coarse candidates kept per (row, half, tile)
#define NTILE (N_PTS / 128)      // 64 column tiles per row
#define CPT   (2 * SELK)         // candidates per (row, tile) = 12

// Static device scratch (no runtime allocation allowed)
__device__ float    g_sq[N_PTS];
__device__ __half   g_xhi[(size_t)N_PTS * DIMK];   // 8 MB
// 32-bit coarse keys: (d2_bits & ~0x7F) | local_col(7b) : 25 MB
__device__ uint32_t g_cand[(size_t)N_PTS * NTILE * CPT];

// ---------------------------------------------------------------------------
// Kernel 1: prep — fp16 hi-part + fp64 squared norms (4-way ILP).
// fp64 stays: g_sq accuracy is load-bearing (R1's flip came from ~2e-4 key
// deviations; fp32 norms would reintroduce ~1e-4-scale risk).
// ---------------------------------------------------------------------------
__global__ void __launch_bounds__(256) prep_kernel(const float* __restrict__ x) {
    int row  = blockIdx.x * 8 + (threadIdx.x >> 5);
    int lane = threadIdx.x & 31;
    const float4* xr = (const float4*)(x + (size_t)row * DIMK);
    double s0 = 0.0, s1 = 0.0, s2 = 0.0, s3 = 0.0;
#pragma unroll
    for (int t = 0; t < 4; t++) {
        int e = lane + t * 32;
        float4 v = xr[e];
        __half h[4];
        h[0] = __float2half_rn(v.x);
        h[1] = __float2half_rn(v.y);
        h[2] = __float2half_rn(v.z);
        h[3] = __float2half_rn(v.w);
        *(uint2*)&g_xhi[(size_t)row * DIMK + e * 4] = *(uint2*)h;
        s0 += (double)v.x * v.x;
        s1 += (double)v.y * v.y;
        s2 += (double)v.z * v.z;
        s3 += (double)v.w * v.w;
    }
    double s = (s0 + s1) + (s2 + s3);
#pragma unroll
    for (int o = 16; o; o >>= 1)
        s += __shfl_xor_sync(0xFFFFFFFFu, s, o);
    if (lane == 0) g_sq[row] = (float)s;
}

// ---------------------------------------------------------------------------
// HMMA helpers (fp16 — the only non-deprioritized legacy mma.sync path:
// s8 measured 4x slower per inst, fp64 ~1/64 rate, tcgen05 unreachable)
// ---------------------------------------------------------------------------
__device__ __forceinline__ void ldsm4_addr(uint32_t& r0, uint32_t& r1,
                                           uint32_t& r2, uint32_t& r3, uint32_t a) {
    asm volatile("ldmatrix.sync.aligned.m8n8.x4.shared.b16 {%0,%1,%2,%3}, [%4];"
                 : "=r"(r0), "=r"(r1), "=r"(r2), "=r"(r3) : "r"(a));
}
__device__ __forceinline__ void ldsm2_addr(uint32_t& r0, uint32_t& r1, uint32_t a) {
    asm volatile("ldmatrix.sync.aligned.m8n8.x2.shared.b16 {%0,%1}, [%2];"
                 : "=r"(r0), "=r"(r1) : "r"(a));
}
__device__ __forceinline__ void mma16816(float c[4], const uint32_t a[4],
                                         const uint32_t b[2]) {
    asm volatile(
        "mma.sync.aligned.m16n8k16.row.col.f32.f16.f16.f32 "
        "{%0,%1,%2,%3}, {%4,%5,%6,%7}, {%8,%9}, {%0,%1,%2,%3};"
        : "+f"(c[0]), "+f"(c[1]), "+f"(c[2]), "+f"(c[3])
        : "r"(a[0]), "r"(a[1]), "r"(a[2]), "r"(a[3]), "r"(b[0]), "r"(b[1]));
}

// ---------------------------------------------------------------------------
// Kernel 2: COARSE hi*hi distance GEMM + fused per-tile candidate selection.
// 3-stage cp.async pipeline, one sync per chunk, occ 2; LAST chunk uses
// wait_group 0 (wait_group 1 would not guarantee the final group landed).
// ---------------------------------------------------------------------------
#define KCHUNK      64
#define NCHUNK      (DIMK / KCHUNK)         // 8
#define MATB        16384                   // 128 rows x 128 B
#define STAGEB      (2 * MATB)              // Ahi + Bhi = 32 KB
#define NSTAGE      3
#define SPITCH      132                     // stage pitch (floats, 16B-aligned)
#define DSMEM_BYTES (NSTAGE * STAGEB)       // 96 KB

__device__ __forceinline__ uint32_t sw128(uint32_t row, uint32_t cb) {
    return row * 128u + (cb ^ ((row & 7u) << 4));
}

__device__ __forceinline__ void issue_chunk(const char* xbase,
                                            const uint32_t srcoff[8],
                                            const uint32_t dstoff[8],
                                            uint32_t bufbase, uint32_t kbyte) {
#pragma unroll
    for (int i = 0; i < 8; i++) {
        asm volatile("cp.async.cg.shared.global [%0], [%1], 16;"
                     :: "r"(bufbase + dstoff[i]),
                        "l"(xbase + srcoff[i] + kbyte));
    }
    asm volatile("cp.async.commit_group;" ::: "memory");
}

// Branch-gated min/max cascade insert into ascending keys[SELK] (32-bit)
__device__ __forceinline__ void ins6u(uint32_t keys[SELK], uint32_t k) {
    if (k < keys[SELK - 1]) {
        uint32_t c = k;
#pragma unroll
        for (int p = 0; p < SELK; p++) {
            uint32_t lo = min(keys[p], c);
            c = max(keys[p], c);
            keys[p] = lo;
        }
    }
}

__global__ void __launch_bounds__(256, 2) dist_mma_kernel() {
    int bid = blockIdx.x;
    int ib = 0, base = 0;
    while (base + (NTILE - ib) <= bid) { base += NTILE - ib; ++ib; }
    int jb = ib + (bid - base);

    extern __shared__ __align__(1024) unsigned char dsm[];
    __shared__ __align__(16) float s_sqi[128];
    __shared__ __align__(16) float s_sqj[128];

    const int i0 = ib * 128;
    const int j0 = jb * 128;
    const int tid  = threadIdx.x;
    const int lane = tid & 31;
    const int warp = tid >> 5;
    const int wm = warp >> 2;
    const int wn = warp & 3;

    const uint32_t dsm_base = (uint32_t)__cvta_generic_to_shared(dsm);

    if (tid < 128) {
        s_sqi[tid] = g_sq[i0 + tid];
        s_sqj[tid] = g_sq[j0 + tid];
    }

    // Hoisted cp.async addressing (per thread, constant across chunks)
    uint32_t srcoff[8], dstoff[8];
#pragma unroll
    for (int i = 0; i < 8; i++) {
        int o   = tid + i * 256;
        int mat = o >> 10;              // 0:Ahi 1:Bhi
        int r   = (o >> 3) & 127;
        int seg = o & 7;
        int rowbase = mat ? j0 : i0;
        srcoff[i] = (uint32_t)(((rowbase + r) * DIMK + seg * 8) * 2);
        dstoff[i] = (uint32_t)(mat * MATB + sw128((uint32_t)r, (uint32_t)(seg * 16)));
    }
    const char* xbase = (const char*)g_xhi;

    float acc[4][4][4];
#pragma unroll
    for (int a = 0; a < 4; a++)
#pragma unroll
        for (int b = 0; b < 4; b++)
#pragma unroll
            for (int c = 0; c < 4; c++) acc[a][b][c] = 0.0f;

    issue_chunk(xbase, srcoff, dstoff, dsm_base, 0);
    issue_chunk(xbase, srcoff, dstoff, dsm_base + STAGEB, KCHUNK * 2);

    const uint32_t Arow = (uint32_t)(wm * 64 + (lane & 15));
    const uint32_t Acb  = (uint32_t)((lane >> 4) * 16);
    const uint32_t Brow = (uint32_t)(wn * 32 + (lane & 7));
    const uint32_t Bcb  = (uint32_t)(((lane >> 3) & 1) * 16);

#pragma unroll
    for (int c = 0; c < NCHUNK; c++) {
        if (c < NCHUNK - 1) asm volatile("cp.async.wait_group 1;" ::: "memory");
        else                asm volatile("cp.async.wait_group 0;" ::: "memory");
        __syncthreads();   // stage c ready; also frees buffer (c-1)%3

        uint32_t stA = dsm_base + (c % NSTAGE) * STAGEB;
        uint32_t stB = stA + MATB;

#pragma unroll
        for (int ks = 0; ks < 4; ks++) {
            uint32_t Ah[4][4], Bh[4][2];
            const uint32_t acol = (uint32_t)(ks * 32) + Acb;
            const uint32_t bcol = (uint32_t)(ks * 32) + Bcb;
#pragma unroll
            for (int mt = 0; mt < 4; mt++)
                ldsm4_addr(Ah[mt][0], Ah[mt][1], Ah[mt][2], Ah[mt][3],
                           stA + sw128(Arow + mt * 16, acol));
#pragma unroll
            for (int nt = 0; nt < 4; nt++)
                ldsm2_addr(Bh[nt][0], Bh[nt][1], stB + sw128(Brow + nt * 8, bcol));
#pragma unroll
            for (int mt = 0; mt < 4; mt++)
#pragma unroll
                for (int nt = 0; nt < 4; nt++)
                    mma16816(acc[mt][nt], Ah[mt], Bh[nt]);

            if (ks == 0 && c + 2 < NCHUNK)
                issue_chunk(xbase, srcoff, dstoff,
                            dsm_base + ((c + 2) % NSTAGE) * STAGEB,
                            (uint32_t)((c + 2) * KCHUNK * 2));
        }
    }
    __syncthreads();   // mainloop reads done before smem reuse as stage

    // Stage raw coarse dot values (float2-packed)
    float (*stage)[SPITCH] = (float(*)[SPITCH])dsm;
    const int r_in = lane >> 2;
    const int c_in = (lane & 3) * 2;
#pragma unroll
    for (int mt = 0; mt < 4; mt++) {
#pragma unroll
        for (int nt = 0; nt < 4; nt++) {
            int r  = wm * 64 + mt * 16 + r_in;
            int cc = wn * 32 + nt * 8 + c_in;
            *(float2*)&stage[r    ][cc] = make_float2(acc[mt][nt][0], acc[mt][nt][1]);
            *(float2*)&stage[r + 8][cc] = make_float2(acc[mt][nt][2], acc[mt][nt][3]);
        }
    }
    __syncthreads();

    const int rl   = tid >> 1;        // 0..127 (row for pass1 / col for pass2)
    const int half = tid & 1;
    const int hb   = half * 64;

    // ---- Pass 1: rows i. d2 = (sq_i - 2*dot) + sq_j ----
    {
        uint32_t keys[SELK];
#pragma unroll
        for (int q = 0; q < SELK; q++) keys[q] = 0xFFFFFFFFu;
        const float sqi_r = s_sqi[rl];
        for (int v4 = 0; v4 < 16; v4++) {
            float4 sv = *(const float4*)&stage[rl][hb + v4 * 4];
            float4 qj = *(const float4*)&s_sqj[hb + v4 * 4];
#pragma unroll
            for (int e = 0; e < 4; e++) {
                float s  = (&sv.x)[e];
                float qq = (&qj.x)[e];
                float d = fmaxf((sqi_r - 2.0f * s) + qq, 0.0f);
                uint32_t k = (__float_as_uint(d) & 0xFFFFFF80u)
                           | (uint32_t)(hb + v4 * 4 + e);
                ins6u(keys, k);
            }
        }
        uint32_t* dst =
            &g_cand[((size_t)(i0 + rl) * NTILE + jb) * CPT + half * SELK];
#pragma unroll
        for (int q = 0; q < SELK; q++) dst[q] = keys[q];
    }

    // ---- Pass 2: rows j (off-diagonal CTAs). d2 = (sq_j - 2*dot) + sq_i ----
    if (ib != jb) {
        uint32_t keys[SELK];
#pragma unroll
        for (int q = 0; q < SELK; q++) keys[q] = 0xFFFFFFFFu;
        const float sqj_c = s_sqj[rl];
        for (int v = 0; v < 64; v++) {
            int il = hb + v;
            float d = fmaxf((sqj_c - 2.0f * stage[il][rl]) + s_sqi[il], 0.0f);
            uint32_t k = (__float_as_uint(d) & 0xFFFFFF80u) | (uint32_t)il;
            ins6u(keys, k);
        }
        uint32_t* dst =
            &g_cand[((size_t)(j0 + rl) * NTILE + ib) * CPT + half * SELK];
#pragma unroll
        for (int q = 0; q < SELK; q++) dst[q] = keys[q];
    }
}

// ---------------------------------------------------------------------------
// Kernel 3 (FUSED): merge 64x12 coarse candidates -> top-16, exact fp32
// refine streamed from L2, select top-10, smooth. One block (128 thr)/row.
// Argmin rounds use 2 barriers (store+reduce) instead of 8.
// ---------------------------------------------------------------------------
__device__ __forceinline__ void ins6ull(unsigned long long keys[SELK],
                                        unsigned long long key) {
    if (key < keys[SELK - 1]) {
        keys[SELK - 1] = key;
#pragma unroll
        for (int p = SELK - 1; p > 0; p--) {
            if (keys[p] < keys[p - 1]) {
                unsigned long long t = keys[p];
                keys[p] = keys[p - 1];
                keys[p - 1] = t;
            }
        }
    }
}

__global__ void __launch_bounds__(128) merge_refine_smooth_kernel(
        const float* __restrict__ x, float* __restrict__ out) {
    const int row = blockIdx.x;
    const int tid = threadIdx.x;
    const int lane = tid & 31;
    const uint32_t* crow = g_cand + (size_t)row * NTILE * CPT;

    __shared__ __align__(16) float s_xi[DIMK];
    __shared__ unsigned long long sdata[128];
    __shared__ int s_idx[NSEL];
    __shared__ unsigned long long s_keys[NSEL];
    __shared__ int s_sel10[KNN];

    ((float4*)s_xi)[tid] = ((const float4*)(x + (size_t)row * DIMK))[tid];

    // Per-thread merge of 6 coarse keys (768 total = 6 x 128)
    unsigned long long keys[SELK];
#pragma unroll
    for (int i = 0; i < SELK; i++) keys[i] = 0xFFFFFFFFFFFFFFFFull;
#pragma unroll
    for (int q = 0; q < SELK; q++) {
        int pos = tid + q * 128;                 // 0..767
        uint32_t k32 = crow[pos];
        int tile = pos / CPT;
        unsigned gcol = (unsigned)(tile * 128) + (k32 & 127u);
        unsigned long long ukey =
            ((unsigned long long)(k32 & 0xFFFFFF80u) << 32) | gcol;
        ins6ull(keys, ukey);
    }

    // 16 rounds of block arg-min (2 barriers/round: warp0 does the reduce)
    for (int r = 0; r < NSEL; r++) {
        sdata[tid] = keys[0];
        __syncthreads();
        if (tid < 32) {
            unsigned long long m = sdata[tid];
            unsigned long long a = sdata[tid + 32];  if (a < m) m = a;
            a = sdata[tid + 64];                     if (a < m) m = a;
            a = sdata[tid + 96];                     if (a < m) m = a;
#pragma unroll
            for (int o = 16; o; o >>= 1) {
                unsigned long long b = __shfl_xor_sync(0xFFFFFFFFu, m, o);
                if (b < m) m = b;
            }
            if (lane == 0) sdata[0] = m;
        }
        __syncthreads();
        unsigned long long win = sdata[0];
        if (tid == 0) s_idx[r] = (int)(win & 0xFFFFFFFFull);
        if (keys[0] == win) {
#pragma unroll
            for (int p = 0; p < SELK - 1; p++) keys[p] = keys[p + 1];
            keys[SELK - 1] = 0xFFFFFFFFFFFFFFFFull;
        }
        __syncthreads();
    }

    // Exact fp32 refine: 8 threads/candidate, rows streamed from L2
    {
        const int c  = tid >> 3;     // candidate 0..15
        const int cs = tid & 7;
        const float4* cr = (const float4*)(x + (size_t)s_idx[c] * DIMK);
        float d0 = 0.0f, d1 = 0.0f, d2a = 0.0f, d3 = 0.0f;
#pragma unroll
        for (int k = 0; k < 16; k++) {
            int q = cs + 8 * k;
            float4 xa = ((const float4*)s_xi)[q];
            float4 xb = cr[q];
            d0  = fmaf(xa.x, xb.x, d0);
            d1  = fmaf(xa.y, xb.y, d1);
            d2a = fmaf(xa.z, xb.z, d2a);
            d3  = fmaf(xa.w, xb.w, d3);
        }
        float dot = (d0 + d1) + (d2a + d3);
#pragma unroll
        for (int off = 4; off; off >>= 1)
            dot += __shfl_down_sync(0xFFFFFFFFu, dot, off, 8);
        if (cs == 0) {
            float d2 = fmaxf((g_sq[row] - 2.0f * dot) + g_sq[s_idx[c]], 0.0f);
            s_keys[c] = ((unsigned long long)__float_as_uint(d2) << 32)
                      | (unsigned)s_idx[c];
        }
    }
    __syncthreads();

    // Thread 0: select 10 smallest exact keys
    if (tid == 0) {
        bool used[NSEL];
#pragma unroll
        for (int c = 0; c < NSEL; c++) used[c] = false;
        for (int r = 0; r < KNN; r++) {
            unsigned long long best = 0xFFFFFFFFFFFFFFFFull;
            int bslot = 0;
            for (int c = 0; c < NSEL; c++) {
                if (!used[c] && s_keys[c] < best) { best = s_keys[c]; bslot = c; }
            }
            used[bslot] = true;
            s_sel10[r] = s_idx[bslot];
        }
    }
    __syncthreads();

    // Smoothing: winners re-read from global (x is 16 MB -> L2 resident)
    float4 acc = make_float4(0.0f, 0.0f, 0.0f, 0.0f);
#pragma unroll
    for (int r = 0; r < KNN; r++) {
        float4 v = ((const float4*)(x + (size_t)s_sel10[r] * DIMK))[tid];
        acc.x += v.x; acc.y += v.y; acc.z += v.z; acc.w += v.w;
    }
    float4 xi = ((const float4*)s_xi)[tid];
    const float w = 0.5f / (float)KNN;
    float4 o;
    o.x = 0.5f * xi.x + w * acc.x;
    o.y = 0.5f * xi.y + w * acc.y;
    o.z = 0.5f * xi.z + w * acc.z;
    o.w = 0.5f * xi.w + w * acc.w;
    ((float4*)(out + (size_t)row * DIMK))[tid] = o;
}

// ---------------------------------------------------------------------------
extern "C" void kernel_launch(void* const* d_in, const int* in_sizes, int n_in,
                              void* d_out, int out_size) {
    const float* x = (const float*)d_in[0];
    float* out = (float*)d_out;

    cudaFuncSetAttribute(dist_mma_kernel,
                         cudaFuncAttributeMaxDynamicSharedMemorySize, DSMEM_BYTES);

    prep_kernel<<<N_PTS / 8, 256>>>(x);
    dist_mma_kernel<<<NTILE * (NTILE + 1) / 2, 256, DSMEM_BYTES>>>();
    merge_refine_smooth_kernel<<<N_PTS, 128>>>(x, out);
}